// round 14
// baseline (speedup 1.0000x reference)
#include <cuda_runtime.h>
#include <float.h>

#define N_  2
#define C_  256
#define H_  56
#define W_  56
#define R_  512
#define P_  7
#define SCALE_ 0.0625f
#define PLANE_ (H_ * W_)      // 3136

// NHWC tensors: [b][hw][c]
__device__ float g_t[(size_t)N_ * PLANE_ * C_];   // features
__device__ float g_h[(size_t)N_ * PLANE_ * C_];   // horiz pairmax
__device__ float g_v[(size_t)N_ * PLANE_ * C_];   // vert  pairmax
__device__ float g_2[(size_t)N_ * PLANE_ * C_];   // 2x2   pairmax

__device__ __forceinline__ float4 fmax4(float4 a, float4 b) {
    return make_float4(fmaxf(a.x,b.x), fmaxf(a.y,b.y), fmaxf(a.z,b.z), fmaxf(a.w,b.w));
}

// ---------- kernel 1: fused NCHW->NHWC transpose + pairmax; 2 output rows/block ----------
__global__ __launch_bounds__(256) void prep_kernel(const float* __restrict__ f)
{
    __shared__ float s[32 * 169];   // [c][3 rows * 56 + pad]; 169 mod 32 = 9 (coprime)
    const int h0 = blockIdx.x * 2;           // 28 blocks in x
    const int c0 = blockIdx.y * 32;
    const int b  = blockIdx.z;
    const int t  = threadIdx.x;

    // load rows h0 .. h0+2 (clamped), contiguous w per (c,row): coalesced
    for (int i = t; i < 32 * 168; i += 256) {
        int c = i / 168, j = i - c * 168;
        int row = min(h0 + j / W_, H_ - 1);
        int w   = j % W_;
        s[c * 169 + j] = __ldg(f + ((size_t)b * C_ + c0 + c) * PLANE_ + row * W_ + w);
    }
    __syncthreads();

    // compute + transposed coalesced writes (c fast across threads)
    for (int i = t; i < 32 * 2 * W_; i += 256) {
        int c    = i & 31;
        int rest = i >> 5;            // 0..111
        int rr   = rest / W_;         // 0..1
        int w    = rest - rr * W_;
        int wr   = min(w + 1, W_ - 1);
        float a  = s[c * 169 + rr * W_ + w];
        float r  = s[c * 169 + rr * W_ + wr];
        float d  = s[c * 169 + (rr + 1) * W_ + w];
        float dr = s[c * 169 + (rr + 1) * W_ + wr];
        float mh = fmaxf(a, r);
        float mv = fmaxf(a, d);
        float m2 = fmaxf(mh, fmaxf(d, dr));
        size_t o = ((size_t)b * PLANE_ + (h0 + rr) * W_ + w) * C_ + c0 + c;
        g_t[o] = a;  g_h[o] = mh;  g_v[o] = mv;  g_2[o] = m2;
    }
}

// ---------- kernel 2: pooling; inline warp-uniform descriptors, occ-forced ----------
__global__ __launch_bounds__(512, 4) void roipool_kernel(
    const float* __restrict__ rois,
    float* __restrict__ out)
{
    __shared__ __align__(16) float stage[128 * P_ * P_];

    const int t    = threadIdx.x;
    const int lane = t & 31;
    const int wrp  = t >> 5;                   // 16 warps
    const int r    = blockIdx.x >> 1;
    const int c0   = (blockIdx.x & 1) * 128;

    // ---- roi constants (warp-uniform, hoisted; exact reference math) ----
    const float* roi = rois + r * 5;
    const int b  = (int)__ldg(roi + 0);                 // trunc == astype(int32)
    const int x1 = __float2int_rn(__ldg(roi + 1) * SCALE_);   // half-even
    const int y1 = __float2int_rn(__ldg(roi + 2) * SCALE_);
    const int x2 = __float2int_rn(__ldg(roi + 3) * SCALE_);
    const int y2 = __float2int_rn(__ldg(roi + 4) * SCALE_);
    const float bin_h = (float)max(y2 - y1 + 1, 1) * (1.0f / P_);
    const float bin_w = (float)max(x2 - x1 + 1, 1) * (1.0f / P_);

    for (int u = wrp; u < P_ * P_; u += 16) {  // <= 4 units/warp, warp-uniform
        int ph = u / P_, pw = u - ph * P_;
        int hs = min(max((int)floorf((float)ph       * bin_h) + y1, 0), H_);
        int he = min(max((int)ceilf ((float)(ph + 1) * bin_h) + y1, 0), H_);
        int ws = min(max((int)floorf((float)pw       * bin_w) + x1, 0), W_);
        int we = min(max((int)ceilf ((float)(pw + 1) * bin_w) + x1, 0), W_);
        int dh = max(he - hs, 0);
        int dw = max(we - ws, 0);
        int ph2 = dh >> 1, th = dh & 1;
        int pw2 = dw >> 1, tw = dw & 1;

        size_t o = ((size_t)b * PLANE_ + hs * W_ + ws) * C_ + c0 + 4 * lane;

        float4 m = make_float4(-FLT_MAX, -FLT_MAX, -FLT_MAX, -FLT_MAX);

        // window = 2x2 quads (g_2) + odd row (g_h) + odd col (g_v) + corner (g_t)
        #pragma unroll
        for (int i = 0; i < 2; ++i)
            #pragma unroll
            for (int j = 0; j < 2; ++j)
                if (i < ph2 && j < pw2)
                    m = fmax4(m, __ldg((const float4*)(g_2 + o + (size_t)(2*i*W_ + 2*j) * C_)));
        #pragma unroll
        for (int j = 0; j < 2; ++j)
            if (th && j < pw2)
                m = fmax4(m, __ldg((const float4*)(g_h + o + (size_t)((dh-1)*W_ + 2*j) * C_)));
        #pragma unroll
        for (int i = 0; i < 2; ++i)
            if (tw && i < ph2)
                m = fmax4(m, __ldg((const float4*)(g_v + o + (size_t)(2*i*W_ + dw-1) * C_)));
        if (th && tw)
            m = fmax4(m, __ldg((const float4*)(g_t + o + (size_t)((dh-1)*W_ + dw-1) * C_)));

        if (dh == 0 || dw == 0) m = make_float4(0.f, 0.f, 0.f, 0.f);

        stage[(4 * lane + 0) * (P_ * P_) + u] = m.x;
        stage[(4 * lane + 1) * (P_ * P_) + u] = m.y;
        stage[(4 * lane + 2) * (P_ * P_) + u] = m.z;
        stage[(4 * lane + 3) * (P_ * P_) + u] = m.w;
    }
    __syncthreads();

    const size_t obase = ((size_t)r * C_ + c0) * (P_ * P_);
    const float4* s4 = (const float4*)stage;
    float4* o4 = (float4*)(out + obase);
    #pragma unroll
    for (int k = 0; k < (128 * P_ * P_ / 4 + 511) / 512; ++k) {
        int i = t + k * 512;
        if (i < 128 * P_ * P_ / 4) o4[i] = s4[i];
    }
}

extern "C" void kernel_launch(void* const* d_in, const int* in_sizes, int n_in,
                              void* d_out, int out_size)
{
    const float* features = (const float*)d_in[0];
    const float* rois     = (const float*)d_in[1];
    float* out            = (float*)d_out;

    dim3 pg(H_ / 2, C_ / 32, N_);             // 28 x 8 x 2 = 448 blocks
    prep_kernel<<<pg, 256>>>(features);

    roipool_kernel<<<R_ * 2, 512>>>(rois, out);   // 1024 blocks
}

// round 15
// speedup vs baseline: 1.0638x; 1.0638x over previous
#include <cuda_runtime.h>
#include <float.h>

#define N_  2
#define C_  256
#define H_  56
#define W_  56
#define R_  512
#define P_  7
#define SCALE_ 0.0625f
#define PLANE_ (H_ * W_)      // 3136
#define C4_    (C_ / 4)       // 64 float4 per cell

// NHWC tensors: [b][hw][c]
__device__ float g_t[(size_t)N_ * PLANE_ * C_];   // features
__device__ float g_h[(size_t)N_ * PLANE_ * C_];   // horiz pairmax
__device__ float g_v[(size_t)N_ * PLANE_ * C_];   // vert  pairmax
__device__ float g_2[(size_t)N_ * PLANE_ * C_];   // 2x2   pairmax

__device__ __forceinline__ float4 fmax4(float4 a, float4 b) {
    return make_float4(fmaxf(a.x,b.x), fmaxf(a.y,b.y), fmaxf(a.z,b.z), fmaxf(a.w,b.w));
}

// ---------- kernel 1: fused NCHW->NHWC transpose + pairmax (round-13 version) ----------
__global__ __launch_bounds__(256) void prep_kernel(const float* __restrict__ f)
{
    __shared__ float s[32 * 113];   // [c][row h | row hd]; stride 113 coprime with 32
    const int h  = blockIdx.x;
    const int c0 = blockIdx.y * 32;
    const int b  = blockIdx.z;
    const int hd = min(h + 1, H_ - 1);
    const int t  = threadIdx.x;

    for (int i = t; i < 32 * 112; i += 256) {
        int c = i / 112, j = i - c * 112;
        int row = (j < W_) ? h : hd;
        int w   = (j < W_) ? j : j - W_;
        s[c * 113 + j] = __ldg(f + ((size_t)b * C_ + c0 + c) * PLANE_ + row * W_ + w);
    }
    __syncthreads();

    for (int i = t; i < 32 * W_; i += 256) {
        int c = i & 31;
        int w = i >> 5;
        int wr = min(w + 1, W_ - 1);
        float a  = s[c * 113 + w];
        float r  = s[c * 113 + wr];
        float d  = s[c * 113 + W_ + w];
        float dr = s[c * 113 + W_ + wr];
        float mh = fmaxf(a, r);
        float mv = fmaxf(a, d);
        float m2 = fmaxf(mh, fmaxf(d, dr));
        size_t o = ((size_t)b * PLANE_ + h * W_ + w) * C_ + c0 + c;
        g_t[o] = a;  g_h[o] = mh;  g_v[o] = mv;  g_2[o] = m2;
    }
}

// ---------- kernel 2: pooling; smem desc table + 32-bit float4 indexing ----------
__global__ __launch_bounds__(512, 4) void roipool_kernel(
    const float* __restrict__ rois,
    float* __restrict__ out)
{
    __shared__ int   sdesc[P_ * P_];
    __shared__ int   sb;
    __shared__ __align__(16) float stage[128 * P_ * P_];

    const int t    = threadIdx.x;
    const int lane = t & 31;
    const int wrp  = t >> 5;                   // 16 warps
    const int r    = blockIdx.x >> 1;
    const int c0q  = (blockIdx.x & 1) * 32;    // C-half in float4 units

    if (t < P_ * P_) {
        const float* roi = rois + r * 5;
        int x1 = __float2int_rn(roi[1] * SCALE_);   // half-even == jnp.round
        int y1 = __float2int_rn(roi[2] * SCALE_);
        int x2 = __float2int_rn(roi[3] * SCALE_);
        int y2 = __float2int_rn(roi[4] * SCALE_);
        float bin_h = (float)max(y2 - y1 + 1, 1) * (1.0f / P_);
        float bin_w = (float)max(x2 - x1 + 1, 1) * (1.0f / P_);

        int ph = t / P_, pw = t - ph * P_;
        int hs = min(max((int)floorf((float)ph       * bin_h) + y1, 0), H_);
        int he = min(max((int)ceilf ((float)(ph + 1) * bin_h) + y1, 0), H_);
        int ws = min(max((int)floorf((float)pw       * bin_w) + x1, 0), W_);
        int we = min(max((int)ceilf ((float)(pw + 1) * bin_w) + x1, 0), W_);

        int dh = max(he - hs, 0);
        int dw = max(we - ws, 0);
        sdesc[t] = (hs * W_ + ws) | (dh << 16) | (dw << 22);
        if (t == 0) sb = (int)roi[0];               // trunc == astype(int32)
    }
    __syncthreads();

    const int bP = sb * PLANE_;                     // warp-uniform
    const float4* t4 = (const float4*)g_t;
    const float4* h4 = (const float4*)g_h;
    const float4* v4 = (const float4*)g_v;
    const float4* q4 = (const float4*)g_2;

    for (int u = wrp; u < P_ * P_; u += 16) {
        int d    = sdesc[u];
        int base =  d        & 0xFFFF;
        int dh   = (d >> 16) & 0x3F;
        int dw   =  d >> 22;
        int ph2 = dh >> 1, th = dh & 1;
        int pw2 = dw >> 1, tw = dw & 1;

        // 32-bit float4 index; constants fold into immediates
        int o  = (bP + base) * C4_ + c0q + lane;    // <= ~401K
        int rh = (dh - 1) * (W_ * C4_);             // odd-row offset
        int cw = (dw - 1) * C4_;                    // odd-col offset

        float4 m = make_float4(-FLT_MAX, -FLT_MAX, -FLT_MAX, -FLT_MAX);

        // window = 2x2 quads (g_2) + odd row (g_h) + odd col (g_v) + corner (g_t)
        #pragma unroll
        for (int i = 0; i < 2; ++i)
            #pragma unroll
            for (int j = 0; j < 2; ++j)
                if (i < ph2 && j < pw2)
                    m = fmax4(m, __ldg(q4 + o + i * (2 * W_ * C4_) + j * (2 * C4_)));
        #pragma unroll
        for (int j = 0; j < 2; ++j)
            if (th && j < pw2)
                m = fmax4(m, __ldg(h4 + o + rh + j * (2 * C4_)));
        #pragma unroll
        for (int i = 0; i < 2; ++i)
            if (tw && i < ph2)
                m = fmax4(m, __ldg(v4 + o + i * (2 * W_ * C4_) + cw));
        if (th && tw)
            m = fmax4(m, __ldg(t4 + o + rh + cw));

        if (dh == 0 || dw == 0) m = make_float4(0.f, 0.f, 0.f, 0.f);

        stage[(4 * lane + 0) * (P_ * P_) + u] = m.x;
        stage[(4 * lane + 1) * (P_ * P_) + u] = m.y;
        stage[(4 * lane + 2) * (P_ * P_) + u] = m.z;
        stage[(4 * lane + 3) * (P_ * P_) + u] = m.w;
    }
    __syncthreads();

    const size_t obase = ((size_t)r * C_ + c0q * 4) * (P_ * P_);
    const float4* s4 = (const float4*)stage;
    float4* o4 = (float4*)(out + obase);
    #pragma unroll
    for (int k = 0; k < (128 * P_ * P_ / 4 + 511) / 512; ++k) {
        int i = t + k * 512;
        if (i < 128 * P_ * P_ / 4) o4[i] = s4[i];
    }
}

extern "C" void kernel_launch(void* const* d_in, const int* in_sizes, int n_in,
                              void* d_out, int out_size)
{
    const float* features = (const float*)d_in[0];
    const float* rois     = (const float*)d_in[1];
    float* out            = (float*)d_out;

    dim3 pg(H_, C_ / 32, N_);                 // 56 x 8 x 2 = 896 blocks
    prep_kernel<<<pg, 256>>>(features);

    roipool_kernel<<<R_ * 2, 512>>>(rois, out);   // 1024 blocks
}